// round 13
// baseline (speedup 1.0000x reference)
#include <cuda_runtime.h>
#include <cuda_bf16.h>

#define N_NODES 100000
#define N_EDGES 6400000
#define MM_BLOCKS   12500        // N_NODES / 8, exact
#define DEG_BLOCKS  25000        // N_EDGES / 256, exact

// ---------------- scratch (allocation-free __device__ globals) ----------------
__device__ int    g_deg [N_NODES];
__device__ float  g_dinv[N_NODES];
__device__ float4 g_p4  [N_NODES];   // raw x@W1 (pre-dinv)
__device__ float4 g_f4  [N_NODES];   // pre-scaled per-node features (width 4)
__device__ float4 g_c4  [N_NODES];   // scatter accumulator (width 4)
__device__ float2 g_f2  [N_NODES];   // width-2 (layer 3)
__device__ float2 g_c2  [N_NODES];

// ---------------- vector reductions (addresses clamped in-bounds) ------------
__device__ __forceinline__ void red_add_v4(float4* addr, float4 v) {
    asm volatile("red.global.add.v4.f32 [%0], {%1,%2,%3,%4};"
                 :: "l"(addr), "f"(v.x), "f"(v.y), "f"(v.z), "f"(v.w) : "memory");
}
__device__ __forceinline__ void red_add_v2(float2* addr, float2 v) {
    asm volatile("red.global.add.v2.f32 [%0], {%1,%2};"
                 :: "l"(addr), "f"(v.x), "f"(v.y) : "memory");
}

__device__ __forceinline__ int clampN(int v) {
    return min(max(v, 0), N_NODES - 1);
}

// ---------------- fused: blocks [0,MM_BLOCKS) do raw mm1; rest do deg count ----
// The two jobs are independent (deg only feeds the later k_scale), so they run
// concurrently in one launch: DRAM-streaming matmul overlaps LTS-atomic counting.
__global__ void k_fused(const float* __restrict__ x, const float* __restrict__ W1,
                        const int* __restrict__ dst) {
    if (blockIdx.x >= MM_BLOCKS) {
        // ---- degree count job ----
        int e = (blockIdx.x - MM_BLOCKS) * blockDim.x + threadIdx.x;
        atomicAdd(&g_deg[clampN(dst[e])], 1);   // e < N_EDGES by construction
        return;
    }
    // ---- raw mm1 job: 8 nodes per block, p4 = x@W1 (no dinv yet) ----
    __shared__ float4 sW[128];                   // W1 rows (128x4)
    __shared__ float  sx[8][128];                // 8 node rows
    int t = threadIdx.x;
    if (t < 128) sW[t] = ((const float4*)W1)[t];

    int base = blockIdx.x * 8;
    float4 v = ((const float4*)(x + (size_t)base * 128))[t];
    ((float4*)sx)[t] = v;
    __syncthreads();

    int warp = t >> 5;
    int lane = t & 31;

    float p0 = 0.f, p1 = 0.f, p2 = 0.f, p3 = 0.f;
#pragma unroll
    for (int i = 0; i < 4; i++) {
        int k = lane + 32 * i;
        float xv = sx[warp][k];
        float4 w = sW[k];
        p0 += xv * w.x; p1 += xv * w.y; p2 += xv * w.z; p3 += xv * w.w;
    }
#pragma unroll
    for (int off = 16; off > 0; off >>= 1) {
        p0 += __shfl_down_sync(0xFFFFFFFFu, p0, off);
        p1 += __shfl_down_sync(0xFFFFFFFFu, p1, off);
        p2 += __shfl_down_sync(0xFFFFFFFFu, p2, off);
        p3 += __shfl_down_sync(0xFFFFFFFFu, p3, off);
    }
    if (lane == 0)
        g_p4[base + warp] = make_float4(p0, p1, p2, p3);
}

// ---------------- scale: dinv = rsqrt(deg+1); f4 = c4 = p4 * dinv --------------
__global__ void k_scale() {
    int n = blockIdx.x * blockDim.x + threadIdx.x;
    if (n >= N_NODES) return;
    float di = rsqrtf((float)(g_deg[n] + 1));    // +1 self-loop
    g_dinv[n] = di;
    float4 p = g_p4[n];
    float4 g = make_float4(p.x * di, p.y * di, p.z * di, p.w * di);
    g_f4[n] = g;
    g_c4[n] = g;                                 // self-loop contribution
}

// ---------------- edge scatter, width 4 ----------------
__global__ void k_edge4(const int* __restrict__ src, const int* __restrict__ dst) {
    int e = blockIdx.x * blockDim.x + threadIdx.x;
    if (e >= N_EDGES) return;
    int s = clampN(src[e]);
    int d = clampN(dst[e]);
    float4 v = g_f4[s];
    red_add_v4(&g_c4[d], v);
}

// ---------------- finalize L1 + matmul L2 (4x4) ----------------
__global__ void k_f1mm2(const float* __restrict__ b1, const float* __restrict__ W2) {
    int n = blockIdx.x * blockDim.x + threadIdx.x;
    if (n >= N_NODES) return;
    float di = g_dinv[n];
    float4 a = g_c4[n];
    float h0 = tanhf(di * a.x + b1[0]);
    float h1 = tanhf(di * a.y + b1[1]);
    float h2 = tanhf(di * a.z + b1[2]);
    float h3 = tanhf(di * a.w + b1[3]);
    float4 g;
    g.x = (h0 * W2[0] + h1 * W2[4] + h2 * W2[8]  + h3 * W2[12]) * di;
    g.y = (h0 * W2[1] + h1 * W2[5] + h2 * W2[9]  + h3 * W2[13]) * di;
    g.z = (h0 * W2[2] + h1 * W2[6] + h2 * W2[10] + h3 * W2[14]) * di;
    g.w = (h0 * W2[3] + h1 * W2[7] + h2 * W2[11] + h3 * W2[15]) * di;
    g_f4[n] = g;
    g_c4[n] = g;                                 // self-loop
}

// ---------------- finalize L2 + matmul L3 (4x2) ----------------
__global__ void k_f2mm3(const float* __restrict__ b2, const float* __restrict__ W3) {
    int n = blockIdx.x * blockDim.x + threadIdx.x;
    if (n >= N_NODES) return;
    float di = g_dinv[n];
    float4 a = g_c4[n];
    float h0 = tanhf(di * a.x + b2[0]);
    float h1 = tanhf(di * a.y + b2[1]);
    float h2 = tanhf(di * a.z + b2[2]);
    float h3 = tanhf(di * a.w + b2[3]);
    float2 g;
    g.x = (h0 * W3[0] + h1 * W3[2] + h2 * W3[4] + h3 * W3[6]) * di;
    g.y = (h0 * W3[1] + h1 * W3[3] + h2 * W3[5] + h3 * W3[7]) * di;
    g_f2[n] = g;
    g_c2[n] = g;                                 // self-loop
}

// ---------------- edge scatter, width 2 ----------------
__global__ void k_edge2(const int* __restrict__ src, const int* __restrict__ dst) {
    int e = blockIdx.x * blockDim.x + threadIdx.x;
    if (e >= N_EDGES) return;
    int s = clampN(src[e]);
    int d = clampN(dst[e]);
    float2 v = g_f2[s];
    red_add_v2(&g_c2[d], v);
}

// ---------------- finalize L3 + classifier ----------------
__global__ void k_final(const float* __restrict__ b3,
                        const float* __restrict__ Wc, const float* __restrict__ bc,
                        float* __restrict__ out, float* __restrict__ hout) {
    int n = blockIdx.x * blockDim.x + threadIdx.x;
    if (n >= N_NODES) return;
    float di = g_dinv[n];
    float2 a = g_c2[n];
    float h0 = tanhf(di * a.x + b3[0]);
    float h1 = tanhf(di * a.y + b3[1]);
    float* o = out + (size_t)n * 10;
#pragma unroll
    for (int j = 0; j < 10; j++)
        o[j] = h0 * Wc[j] + h1 * Wc[10 + j] + bc[j];
    hout[2 * n + 0] = h0;
    hout[2 * n + 1] = h1;
}

// ---------------- launch ----------------
extern "C" void kernel_launch(void* const* d_in, const int* in_sizes, int n_in,
                              void* d_out, int out_size) {
    const float* x  = (const float*)d_in[0];
    const int*   ei = (const int*)d_in[1];        // int32, [2, E] row-major
    const float* W1 = (const float*)d_in[2];
    const float* b1 = (const float*)d_in[3];
    const float* W2 = (const float*)d_in[4];
    const float* b2 = (const float*)d_in[5];
    const float* W3 = (const float*)d_in[6];
    const float* b3 = (const float*)d_in[7];
    const float* Wc = (const float*)d_in[8];
    const float* bc = (const float*)d_in[9];

    const int* src = ei;            // row 0
    const int* dst = ei + N_EDGES;  // row 1

    float* out  = (float*)d_out;                  // [N, 10]
    float* hout = out + (size_t)N_NODES * 10;     // [N, 2]

    // zero degree counters (graph-capturable, no allocation)
    void* degPtr = nullptr;
    cudaGetSymbolAddress(&degPtr, g_deg);
    cudaMemsetAsync(degPtr, 0, N_NODES * sizeof(int));

    const int T = 256;
    const int nodeBlocks = (N_NODES + T - 1) / T;
    const int edgeBlocks = (N_EDGES + T - 1) / T;

    k_fused <<<MM_BLOCKS + DEG_BLOCKS, T>>>(x, W1, dst);  // mm1-raw ∥ deg_count
    k_scale <<<nodeBlocks, T>>>();

    k_edge4 <<<edgeBlocks, T>>>(src, dst);
    k_f1mm2 <<<nodeBlocks, T>>>(b1, W2);

    k_edge4 <<<edgeBlocks, T>>>(src, dst);
    k_f2mm3 <<<nodeBlocks, T>>>(b2, W3);

    k_edge2 <<<edgeBlocks, T>>>(src, dst);
    k_final <<<nodeBlocks, T>>>(b3, Wc, bc, out, hout);
}